// round 15
// baseline (speedup 1.0000x reference)
#include <cuda_runtime.h>
#include <cuda_bf16.h>
#include <cuda_fp16.h>

#define N_NODES    200000
#define NUM_GRAPHS 2000
#define VOCAB      10000
#define D          64
#define NT         4     // nodes per thread (gemm kernels)
#define CAP        64    // fixed per-node edge bucket capacity (P(deg>64)<1e-35)

// ---------------- scratch (static device globals; no allocation) ------------
__device__ __half g_T1h [(size_t)VOCAB * D];    // embed_table @ W1 (fp16 storage)
__device__ __half g_bufAh[(size_t)N_NODES * D]; // layer-2 ts (fp16 storage)
__device__ float  g_bufB[(size_t)N_NODES * D];  // h (layer-1 activations, fp32)
__device__ float  g_dinv[N_NODES];
__device__ int    g_deg [N_NODES];              // in-degree (== cursor after fill)
__device__ int    g_cursor[N_NODES];
__device__ int    g_csr[(size_t)N_NODES * CAP]; // fixed-stride edge buckets
__device__ float  g_gsum[NUM_GRAPHS * D];
__device__ float  g_gcnt[NUM_GRAPHS];

// vectorized no-return global reduction (sm_90+)
__device__ __forceinline__ void red_add_v4(float* addr, float4 v) {
    asm volatile("red.global.add.v4.f32 [%0], {%1, %2, %3, %4};"
                 :: "l"(addr), "f"(v.x), "f"(v.y), "f"(v.z), "f"(v.w)
                 : "memory");
}

// ---------------- packed f32x2 helpers (sm_103a FFMA2 path) -----------------
__device__ __forceinline__ unsigned long long pack2(float v) {
    unsigned long long r;
    asm("mov.b64 %0, {%1, %1};" : "=l"(r) : "f"(v));
    return r;
}
__device__ __forceinline__ void ffma2(unsigned long long& d,
                                      unsigned long long a,
                                      unsigned long long b) {
    asm("fma.rn.f32x2 %0, %1, %2, %0;" : "+l"(d) : "l"(a), "l"(b));
}
__device__ __forceinline__ void mul2(unsigned long long& d,
                                     unsigned long long a) {
    asm("mul.rn.f32x2 %0, %0, %1;" : "+l"(d) : "l"(a));
}

// ---------------- fp16 payload helpers --------------------------------------
__device__ __forceinline__ float4 h4_to_f4(unsigned long long v) {
    union { unsigned long long u; __half2 h[2]; } cv;
    cv.u = v;
    float2 f0 = __half22float2(cv.h[0]);
    float2 f1 = __half22float2(cv.h[1]);
    return make_float4(f0.x, f0.y, f1.x, f1.y);
}
__device__ __forceinline__ unsigned int f32x2_to_h2(unsigned long long p) {
    union { unsigned long long u; float f[2]; } cv;
    cv.u = p;
    __half2 h = __float22half2_rn(make_float2(cv.f[0], cv.f[1]));
    return *reinterpret_cast<unsigned int*>(&h);
}

// ---------------- init: zero cursor / gsum / gcnt ---------------------------
__global__ void k_init() {
    int t = blockIdx.x * blockDim.x + threadIdx.x;
    if (t < N_NODES)        g_cursor[t] = 0;
    if (t < NUM_GRAPHS * D) g_gsum[t] = 0.0f;
    if (t < NUM_GRAPHS)     g_gcnt[t] = 0.0f;
}

// ---------------- fill fixed-stride buckets (no scan needed) ----------------
__global__ void k_fill(const int* __restrict__ src, const int* __restrict__ dst, int E) {
    int e = blockIdx.x * blockDim.x + threadIdx.x;
    if (e >= E) return;
    int d = dst[e];
    int pos = atomicAdd(&g_cursor[d], 1);
    if (pos < CAP) g_csr[(size_t)d * CAP + pos] = src[e];
}

__global__ void k_dinv() {
    int t = blockIdx.x * blockDim.x + threadIdx.x;
    if (t >= N_NODES) return;
    int dg = g_cursor[t];
    g_deg[t]  = dg;
    g_dinv[t] = rsqrtf((float)(dg + 1));   // +1 self loop (true degree)
}

// FFMA2 k-slice, 16 cols/thread
#define KSTEP2(R, COMP)                                                       \
    {                                                                         \
        const ulonglong2* wr =                                                \
            (const ulonglong2*)&Ws[(k4 * 4 + (R)) * 16 + q * 4];              \
        ulonglong2 wv0 = wr[0], wv1 = wr[1], wv2 = wr[2], wv3 = wr[3];        \
        _Pragma("unroll")                                                     \
        for (int i = 0; i < NT; i++) {                                        \
            unsigned long long hs2 = pack2(h[i].COMP);                        \
            ffma2(acc2[i][0], hs2, wv0.x);                                    \
            ffma2(acc2[i][1], hs2, wv0.y);                                    \
            ffma2(acc2[i][2], hs2, wv1.x);                                    \
            ffma2(acc2[i][3], hs2, wv1.y);                                    \
            ffma2(acc2[i][4], hs2, wv2.x);                                    \
            ffma2(acc2[i][5], hs2, wv2.y);                                    \
            ffma2(acc2[i][6], hs2, wv3.x);                                    \
            ffma2(acc2[i][7], hs2, wv3.y);                                    \
        }                                                                     \
    }

// ---------------- T1 = embed_table @ W1  (VOCAB x 64, fp16 out) -------------
__global__ void __launch_bounds__(256, 2)
k_t1(const float* __restrict__ table, const float* __restrict__ W) {
    __shared__ float4 Ws[D * 16];   // W row-major: Ws[k*16 + j4]
    for (int t = threadIdx.x; t < D * 16; t += 256)
        Ws[t] = ((const float4*)W)[t];
    __syncthreads();

    int T    = blockIdx.x * 256 + threadIdx.x;
    int lane = threadIdx.x & 31;
    int q    = lane & 3;
    int r8   = lane >> 2;
    int wb   = (T >> 5) * 32;

    int n[NT];
    const float4* hrow[NT];
    #pragma unroll
    for (int i = 0; i < NT; i++) {
        n[i] = wb + r8 + i * 8;
        int ns = (n[i] < VOCAB) ? n[i] : 0;
        hrow[i] = (const float4*)(table + (size_t)ns * D);
    }

    unsigned long long acc2[NT][8];
    #pragma unroll
    for (int i = 0; i < NT; i++)
        #pragma unroll
        for (int j = 0; j < 8; j++) acc2[i][j] = 0ull;

    #pragma unroll 4
    for (int k4 = 0; k4 < 16; k4++) {
        float4 h[NT];
        #pragma unroll
        for (int i = 0; i < NT; i++) h[i] = hrow[i][k4];
        KSTEP2(0, x)
        KSTEP2(1, y)
        KSTEP2(2, z)
        KSTEP2(3, w)
    }

    #pragma unroll
    for (int i = 0; i < NT; i++) {
        if (n[i] >= VOCAB) continue;
        uint4* O = (uint4*)(g_T1h + (size_t)n[i] * D) + q * 2;
        O[0] = make_uint4(f32x2_to_h2(acc2[i][0]), f32x2_to_h2(acc2[i][1]),
                          f32x2_to_h2(acc2[i][2]), f32x2_to_h2(acc2[i][3]));
        O[1] = make_uint4(f32x2_to_h2(acc2[i][4]), f32x2_to_h2(acc2[i][5]),
                          f32x2_to_h2(acc2[i][6]), f32x2_to_h2(acc2[i][7]));
    }
}

// ---- gather layer 1: h = relu(di*(di*T1[x_i] + Σ dinv[s]*T1[x[s]]) + b1) ---
// One warp per node; manual 2-way software pipelining. fp16 rows, fp32 acc.
__global__ void __launch_bounds__(256)
k_gather1(const int* __restrict__ x, const float* __restrict__ bias) {
    int warp = (blockIdx.x * blockDim.x + threadIdx.x) >> 5;
    if (warp >= N_NODES) return;
    int lane = threadIdx.x & 31;
    int half = lane >> 4;
    int c    = lane & 15;

    size_t s0 = (size_t)warp * CAP;
    int dg = g_deg[warp];
    if (dg > CAP) dg = CAP;

    float4 acc0 = make_float4(0.f, 0.f, 0.f, 0.f);
    float4 acc1 = make_float4(0.f, 0.f, 0.f, 0.f);
    int e = half;
    for (; e + 2 < dg; e += 4) {
        int sA = __ldg(&g_csr[s0 + e]);
        int sB = __ldg(&g_csr[s0 + e + 2]);
        int xA = __ldg(x + sA);
        int xB = __ldg(x + sB);
        float dA = __ldg(&g_dinv[sA]);
        float dB = __ldg(&g_dinv[sB]);
        unsigned long long rA =
            ((const unsigned long long*)(g_T1h + (size_t)xA * D))[c];
        unsigned long long rB =
            ((const unsigned long long*)(g_T1h + (size_t)xB * D))[c];
        float4 vA = h4_to_f4(rA);
        float4 vB = h4_to_f4(rB);
        acc0.x += dA * vA.x; acc0.y += dA * vA.y;
        acc0.z += dA * vA.z; acc0.w += dA * vA.w;
        acc1.x += dB * vB.x; acc1.y += dB * vB.y;
        acc1.z += dB * vB.z; acc1.w += dB * vB.w;
    }
    if (e < dg) {
        int s  = __ldg(&g_csr[s0 + e]);
        int xi = __ldg(x + s);
        float ds = __ldg(&g_dinv[s]);
        float4 v = h4_to_f4(
            ((const unsigned long long*)(g_T1h + (size_t)xi * D))[c]);
        acc0.x += ds * v.x; acc0.y += ds * v.y;
        acc0.z += ds * v.z; acc0.w += ds * v.w;
    }
    float4 acc;
    acc.x = acc0.x + acc1.x; acc.y = acc0.y + acc1.y;
    acc.z = acc0.z + acc1.z; acc.w = acc0.w + acc1.w;

    acc.x += __shfl_down_sync(0xffffffffu, acc.x, 16);
    acc.y += __shfl_down_sync(0xffffffffu, acc.y, 16);
    acc.z += __shfl_down_sync(0xffffffffu, acc.z, 16);
    acc.w += __shfl_down_sync(0xffffffffu, acc.w, 16);

    if (half == 0) {
        float di = g_dinv[warp];
        int xi = __ldg(x + warp);
        float4 a = h4_to_f4(
            ((const unsigned long long*)(g_T1h + (size_t)xi * D))[c]);
        float4 bb = __ldg((const float4*)bias + c);
        float4 h;
        h.x = fmaxf(di * (di * a.x + acc.x) + bb.x, 0.f);
        h.y = fmaxf(di * (di * a.y + acc.y) + bb.y, 0.f);
        h.z = fmaxf(di * (di * a.z + acc.z) + bb.z, 0.f);
        h.w = fmaxf(di * (di * a.w + acc.w) + bb.w, 0.f);
        ((float4*)g_bufB)[(size_t)warp * 16 + c] = h;
    }
}

// ---------------- GEMM layer 2: Ah = dinv * (h @ W2),  h = bufB -------------
// R7-validated internals (NT=4, 16 cols/thread, 2 blocks/SM); fp16 epilogue.
__global__ void __launch_bounds__(256, 2)
k_gemm2(const float* __restrict__ W) {
    __shared__ float4 Ws[D * 16];
    for (int t = threadIdx.x; t < D * 16; t += 256)
        Ws[t] = ((const float4*)W)[t];
    __syncthreads();

    int T    = blockIdx.x * 256 + threadIdx.x;
    int lane = threadIdx.x & 31;
    int q    = lane & 3;
    int r8   = lane >> 2;
    int wb   = (T >> 5) * 32;

    int n[NT];
    const float4* hrow[NT];
    #pragma unroll
    for (int i = 0; i < NT; i++) {
        n[i] = wb + r8 + i * 8;
        int ns = (n[i] < N_NODES) ? n[i] : 0;
        hrow[i] = (const float4*)g_bufB + (size_t)ns * 16;
    }

    unsigned long long acc2[NT][8];
    #pragma unroll
    for (int i = 0; i < NT; i++)
        #pragma unroll
        for (int j = 0; j < 8; j++) acc2[i][j] = 0ull;

    #pragma unroll 4
    for (int k4 = 0; k4 < 16; k4++) {
        float4 h[NT];
        #pragma unroll
        for (int i = 0; i < NT; i++) h[i] = hrow[i][k4];
        KSTEP2(0, x)
        KSTEP2(1, y)
        KSTEP2(2, z)
        KSTEP2(3, w)
    }

    #pragma unroll
    for (int i = 0; i < NT; i++) {
        if (n[i] >= N_NODES) continue;
        unsigned long long di2 = pack2(g_dinv[n[i]]);
        #pragma unroll
        for (int j = 0; j < 8; j++) mul2(acc2[i][j], di2);
        uint4* A = (uint4*)(g_bufAh + (size_t)n[i] * D) + q * 2;
        A[0] = make_uint4(f32x2_to_h2(acc2[i][0]), f32x2_to_h2(acc2[i][1]),
                          f32x2_to_h2(acc2[i][2]), f32x2_to_h2(acc2[i][3]));
        A[1] = make_uint4(f32x2_to_h2(acc2[i][4]), f32x2_to_h2(acc2[i][5]),
                          f32x2_to_h2(acc2[i][6]), f32x2_to_h2(acc2[i][7]));
    }
}

// ------- gather layer 2 + pool: gsum[b] += relu(dinv*(A_i+agg)+b2) ----------
__global__ void __launch_bounds__(256)
k_gather2(const int* __restrict__ batch, const float* __restrict__ bias) {
    int warp = (blockIdx.x * blockDim.x + threadIdx.x) >> 5;
    if (warp >= N_NODES) return;
    int lane = threadIdx.x & 31;
    int half = lane >> 4;
    int c    = lane & 15;

    size_t s0 = (size_t)warp * CAP;
    int dg = g_deg[warp];
    if (dg > CAP) dg = CAP;

    float4 acc0 = make_float4(0.f, 0.f, 0.f, 0.f);
    float4 acc1 = make_float4(0.f, 0.f, 0.f, 0.f);
    int e = half;
    for (; e + 2 < dg; e += 4) {
        int sA = __ldg(&g_csr[s0 + e]);
        int sB = __ldg(&g_csr[s0 + e + 2]);
        unsigned long long rA =
            ((const unsigned long long*)(g_bufAh + (size_t)sA * D))[c];
        unsigned long long rB =
            ((const unsigned long long*)(g_bufAh + (size_t)sB * D))[c];
        float4 vA = h4_to_f4(rA);
        float4 vB = h4_to_f4(rB);
        acc0.x += vA.x; acc0.y += vA.y; acc0.z += vA.z; acc0.w += vA.w;
        acc1.x += vB.x; acc1.y += vB.y; acc1.z += vB.z; acc1.w += vB.w;
    }
    if (e < dg) {
        int s = __ldg(&g_csr[s0 + e]);
        float4 v = h4_to_f4(
            ((const unsigned long long*)(g_bufAh + (size_t)s * D))[c]);
        acc0.x += v.x; acc0.y += v.y; acc0.z += v.z; acc0.w += v.w;
    }
    float4 acc;
    acc.x = acc0.x + acc1.x; acc.y = acc0.y + acc1.y;
    acc.z = acc0.z + acc1.z; acc.w = acc0.w + acc1.w;

    acc.x += __shfl_down_sync(0xffffffffu, acc.x, 16);
    acc.y += __shfl_down_sync(0xffffffffu, acc.y, 16);
    acc.z += __shfl_down_sync(0xffffffffu, acc.z, 16);
    acc.w += __shfl_down_sync(0xffffffffu, acc.w, 16);

    if (half == 0) {
        float di = g_dinv[warp];
        int b = __ldg(batch + warp);
        float4 a = h4_to_f4(
            ((const unsigned long long*)(g_bufAh + (size_t)warp * D))[c]);
        float4 bb = __ldg((const float4*)bias + c);
        float4 v;
        v.x = fmaxf(di * (a.x + acc.x) + bb.x, 0.f);
        v.y = fmaxf(di * (a.y + acc.y) + bb.y, 0.f);
        v.z = fmaxf(di * (a.z + acc.z) + bb.z, 0.f);
        v.w = fmaxf(di * (a.w + acc.w) + bb.w, 0.f);
        red_add_v4(&g_gsum[b * D + c * 4], v);
        if (c == 0) atomicAdd(&g_gcnt[b], 1.0f);
    }
}

// ---------------- head: out[g] = (gsum[g]/cnt) @ Wlin + blin ----------------
__global__ void k_final(const float* __restrict__ Wlin,
                        const float* __restrict__ blin,
                        float* __restrict__ out) {
    int g = blockIdx.x * blockDim.x + threadIdx.x;
    if (g >= NUM_GRAPHS) return;
    float inv = 1.0f / fmaxf(g_gcnt[g], 1.0f);
    float a0 = blin[0], a1 = blin[1];
    #pragma unroll
    for (int j = 0; j < D; j++) {
        float v = g_gsum[g * D + j] * inv;
        a0 += v * Wlin[2 * j + 0];
        a1 += v * Wlin[2 * j + 1];
    }
    out[2 * g + 0] = a0;
    out[2 * g + 1] = a1;
}

// ---------------- launch ----------------------------------------------------
extern "C" void kernel_launch(void* const* d_in, const int* in_sizes, int n_in,
                              void* d_out, int out_size) {
    const int*   x     = (const int*)  d_in[0];
    const int*   ei    = (const int*)  d_in[1];
    const int*   batch = (const int*)  d_in[3];
    const float* table = (const float*)d_in[4];
    const float* W1    = (const float*)d_in[5];
    const float* b1    = (const float*)d_in[6];
    const float* W2    = (const float*)d_in[7];
    const float* b2    = (const float*)d_in[8];
    const float* Wlin  = (const float*)d_in[9];
    const float* blin  = (const float*)d_in[10];
    float*       out   = (float*)d_out;

    int E = in_sizes[1] / 2;
    const int* src = ei;       // edge_index[0]
    const int* dst = ei + E;   // edge_index[1]

    const int TPB = 256;
    int gbN = (N_NODES + TPB - 1) / TPB;                         // 782
    int gbE = (E + TPB - 1) / TPB;
    int gbW = (int)(((long long)N_NODES * 32 + TPB - 1) / TPB);  // warp/node
    int gbV = (VOCAB + TPB - 1) / TPB;                           // 40

    // Fork: bucket build (branch A) || T1 transform (branch B).
    cudaStream_t s2;
    cudaEvent_t evFork, evJoin;
    cudaStreamCreateWithFlags(&s2, cudaStreamNonBlocking);
    cudaEventCreateWithFlags(&evFork, cudaEventDisableTiming);
    cudaEventCreateWithFlags(&evJoin, cudaEventDisableTiming);

    cudaEventRecord(evFork, 0);
    cudaStreamWaitEvent(s2, evFork, 0);

    // branch A (s2): scan-free bucket build + dinv
    k_init<<<gbN, TPB, 0, s2>>>();
    k_fill<<<gbE, TPB, 0, s2>>>(src, dst, E);
    k_dinv<<<gbN, TPB, 0, s2>>>();

    // branch B (main stream): tiny vocab-level transform
    k_t1<<<gbV, TPB>>>(table, W1);                 // T1h = table @ W1 (fp16)

    // join
    cudaEventRecord(evJoin, s2);
    cudaStreamWaitEvent(0, evJoin, 0);

    k_gather1<<<gbW, TPB>>>(x, b1);                // B = relu(di*(di*T1[x_i]+Σ ds*T1[xs])+b1)
    k_gemm2<<<gbN, TPB>>>(W2);                     // Ah = dinv*(B@W2)  (fp16 out)
    k_gather2<<<gbW, TPB>>>(batch, b2);            // gsum += relu(dinv*(A_i+ΣA_s)+b2)
    k_final<<<(NUM_GRAPHS + TPB - 1) / TPB, TPB>>>(Wlin, blin, out);

    cudaEventDestroy(evFork);
    cudaEventDestroy(evJoin);
    cudaStreamDestroy(s2);
}

// round 16
// speedup vs baseline: 1.2170x; 1.2170x over previous
#include <cuda_runtime.h>
#include <cuda_bf16.h>
#include <cuda_fp16.h>

#define N_NODES    200000
#define NUM_GRAPHS 2000
#define VOCAB      10000
#define D          64
#define NT         4     // nodes per thread (T1 kernel)
#define MAX_E      1600000
#define SCAN_B     256
#define NB_SCAN    ((N_NODES + SCAN_B - 1) / SCAN_B)   // 782

// ---------------- scratch (static device globals; no allocation) ------------
__device__ __half g_T1h [(size_t)VOCAB * D];    // embed_table @ W1 (fp16 storage)
__device__ __half g_bufAh[(size_t)N_NODES * D]; // layer-2 ts (fp16 storage)
__device__ float  g_bufB[(size_t)N_NODES * D];  // h (layer-1 activations, fp32)
__device__ float  g_dinv[N_NODES];
__device__ int    g_deg [N_NODES];
__device__ int    g_start[N_NODES];             // CSR row offsets (by dst)
__device__ int    g_cursor[N_NODES];
__device__ int    g_csr[MAX_E];                 // src indices bucketed by dst
__device__ int    g_bsum[NB_SCAN];
__device__ float  g_gsum[NUM_GRAPHS * D];
__device__ float  g_gcnt[NUM_GRAPHS];

// vectorized no-return global reduction (sm_90+)
__device__ __forceinline__ void red_add_v4(float* addr, float4 v) {
    asm volatile("red.global.add.v4.f32 [%0], {%1, %2, %3, %4};"
                 :: "l"(addr), "f"(v.x), "f"(v.y), "f"(v.z), "f"(v.w)
                 : "memory");
}

// ---------------- packed f32x2 helpers (sm_103a FFMA2 path) -----------------
__device__ __forceinline__ unsigned long long pack2(float v) {
    unsigned long long r;
    asm("mov.b64 %0, {%1, %1};" : "=l"(r) : "f"(v));
    return r;
}
__device__ __forceinline__ void ffma2(unsigned long long& d,
                                      unsigned long long a,
                                      unsigned long long b) {
    asm("fma.rn.f32x2 %0, %1, %2, %0;" : "+l"(d) : "l"(a), "l"(b));
}

// ---------------- fp16 / tf32 helpers ---------------------------------------
__device__ __forceinline__ float4 h4_to_f4(unsigned long long v) {
    union { unsigned long long u; __half2 h[2]; } cv;
    cv.u = v;
    float2 f0 = __half22float2(cv.h[0]);
    float2 f1 = __half22float2(cv.h[1]);
    return make_float4(f0.x, f0.y, f1.x, f1.y);
}
__device__ __forceinline__ unsigned int f32x2_to_h2(unsigned long long p) {
    union { unsigned long long u; float f[2]; } cv;
    cv.u = p;
    __half2 h = __float22half2_rn(make_float2(cv.f[0], cv.f[1]));
    return *reinterpret_cast<unsigned int*>(&h);
}
__device__ __forceinline__ unsigned cvt_tf32(float f) {
    unsigned r;
    asm("cvt.rna.tf32.f32 %0, %1;" : "=r"(r) : "f"(f));
    return r;
}

// ---------------- init: zero deg / gsum / gcnt ------------------------------
__global__ void k_init() {
    int t = blockIdx.x * blockDim.x + threadIdx.x;
    if (t < N_NODES)        g_deg[t]  = 0;
    if (t < NUM_GRAPHS * D) g_gsum[t] = 0.0f;
    if (t < NUM_GRAPHS)     g_gcnt[t] = 0.0f;
}

// ---------------- degree (in-degree over dst) -------------------------------
__global__ void k_deg(const int* __restrict__ dst, int E) {
    int e = blockIdx.x * blockDim.x + threadIdx.x;
    if (e < E) atomicAdd(&g_deg[dst[e]], 1);
}

// ---------------- CSR build: scan + fill ------------------------------------
__global__ void k_scan1() {
    __shared__ int s[SCAN_B];
    int tid = threadIdx.x;
    int t = blockIdx.x * SCAN_B + tid;
    int v = (t < N_NODES) ? g_deg[t] : 0;
    s[tid] = v;
    __syncthreads();
    #pragma unroll
    for (int o = 1; o < SCAN_B; o <<= 1) {
        int u = (tid >= o) ? s[tid - o] : 0;
        __syncthreads();
        s[tid] += u;
        __syncthreads();
    }
    if (t < N_NODES) g_start[t] = s[tid] - v;     // exclusive
    if (tid == SCAN_B - 1) g_bsum[blockIdx.x] = s[tid];
}

__global__ void k_scan2() {
    __shared__ int s[1024];
    int tid = threadIdx.x;
    int v = (tid < NB_SCAN) ? g_bsum[tid] : 0;
    s[tid] = v;
    __syncthreads();
    #pragma unroll
    for (int o = 1; o < 1024; o <<= 1) {
        int u = (tid >= o) ? s[tid - o] : 0;
        __syncthreads();
        s[tid] += u;
        __syncthreads();
    }
    if (tid < NB_SCAN) g_bsum[tid] = s[tid] - v;  // exclusive block offsets
}

__global__ void k_scan3() {
    int t = blockIdx.x * blockDim.x + threadIdx.x;
    if (t >= N_NODES) return;
    int st = g_start[t] + g_bsum[blockIdx.x];
    g_start[t]  = st;
    g_cursor[t] = st;
    g_dinv[t]   = rsqrtf((float)(g_deg[t] + 1));  // +1 self loop
}

__global__ void k_fill(const int* __restrict__ src, const int* __restrict__ dst, int E) {
    int e = blockIdx.x * blockDim.x + threadIdx.x;
    if (e >= E) return;
    int d = dst[e];
    int pos = atomicAdd(&g_cursor[d], 1);
    g_csr[pos] = src[e];
}

// FFMA2 k-slice, 16 cols/thread (T1 kernel)
#define KSTEP2(R, COMP)                                                       \
    {                                                                         \
        const ulonglong2* wr =                                                \
            (const ulonglong2*)&Ws[(k4 * 4 + (R)) * 16 + q * 4];              \
        ulonglong2 wv0 = wr[0], wv1 = wr[1], wv2 = wr[2], wv3 = wr[3];        \
        _Pragma("unroll")                                                     \
        for (int i = 0; i < NT; i++) {                                        \
            unsigned long long hs2 = pack2(h[i].COMP);                        \
            ffma2(acc2[i][0], hs2, wv0.x);                                    \
            ffma2(acc2[i][1], hs2, wv0.y);                                    \
            ffma2(acc2[i][2], hs2, wv1.x);                                    \
            ffma2(acc2[i][3], hs2, wv1.y);                                    \
            ffma2(acc2[i][4], hs2, wv2.x);                                    \
            ffma2(acc2[i][5], hs2, wv2.y);                                    \
            ffma2(acc2[i][6], hs2, wv3.x);                                    \
            ffma2(acc2[i][7], hs2, wv3.y);                                    \
        }                                                                     \
    }

// ---------------- T1 = embed_table @ W1  (VOCAB x 64, fp16 out) -------------
__global__ void __launch_bounds__(256, 2)
k_t1(const float* __restrict__ table, const float* __restrict__ W) {
    __shared__ float4 Ws[D * 16];   // W row-major: Ws[k*16 + j4]
    for (int t = threadIdx.x; t < D * 16; t += 256)
        Ws[t] = ((const float4*)W)[t];
    __syncthreads();

    int T    = blockIdx.x * 256 + threadIdx.x;
    int lane = threadIdx.x & 31;
    int q    = lane & 3;
    int r8   = lane >> 2;
    int wb   = (T >> 5) * 32;

    int n[NT];
    const float4* hrow[NT];
    #pragma unroll
    for (int i = 0; i < NT; i++) {
        n[i] = wb + r8 + i * 8;
        int ns = (n[i] < VOCAB) ? n[i] : 0;
        hrow[i] = (const float4*)(table + (size_t)ns * D);
    }

    unsigned long long acc2[NT][8];
    #pragma unroll
    for (int i = 0; i < NT; i++)
        #pragma unroll
        for (int j = 0; j < 8; j++) acc2[i][j] = 0ull;

    #pragma unroll 4
    for (int k4 = 0; k4 < 16; k4++) {
        float4 h[NT];
        #pragma unroll
        for (int i = 0; i < NT; i++) h[i] = hrow[i][k4];
        KSTEP2(0, x)
        KSTEP2(1, y)
        KSTEP2(2, z)
        KSTEP2(3, w)
    }

    #pragma unroll
    for (int i = 0; i < NT; i++) {
        if (n[i] >= VOCAB) continue;
        uint4* O = (uint4*)(g_T1h + (size_t)n[i] * D) + q * 2;
        O[0] = make_uint4(f32x2_to_h2(acc2[i][0]), f32x2_to_h2(acc2[i][1]),
                          f32x2_to_h2(acc2[i][2]), f32x2_to_h2(acc2[i][3]));
        O[1] = make_uint4(f32x2_to_h2(acc2[i][4]), f32x2_to_h2(acc2[i][5]),
                          f32x2_to_h2(acc2[i][6]), f32x2_to_h2(acc2[i][7]));
    }
}

// ---- gather layer 1: h = relu(di*(di*T1[x_i] + Σ dinv[s]*T1[x[s]]) + b1) ---
// One warp per node; manual 2-way software pipelining. fp16 rows, fp32 acc.
__global__ void __launch_bounds__(256)
k_gather1(const int* __restrict__ x, const float* __restrict__ bias) {
    int warp = (blockIdx.x * blockDim.x + threadIdx.x) >> 5;
    if (warp >= N_NODES) return;
    int lane = threadIdx.x & 31;
    int half = lane >> 4;
    int c    = lane & 15;

    int s0 = g_start[warp];
    int dg = g_deg[warp];

    float4 acc0 = make_float4(0.f, 0.f, 0.f, 0.f);
    float4 acc1 = make_float4(0.f, 0.f, 0.f, 0.f);
    int e = half;
    for (; e + 2 < dg; e += 4) {
        int sA = __ldg(&g_csr[s0 + e]);
        int sB = __ldg(&g_csr[s0 + e + 2]);
        int xA = __ldg(x + sA);
        int xB = __ldg(x + sB);
        float dA = __ldg(&g_dinv[sA]);
        float dB = __ldg(&g_dinv[sB]);
        unsigned long long rA =
            ((const unsigned long long*)(g_T1h + (size_t)xA * D))[c];
        unsigned long long rB =
            ((const unsigned long long*)(g_T1h + (size_t)xB * D))[c];
        float4 vA = h4_to_f4(rA);
        float4 vB = h4_to_f4(rB);
        acc0.x += dA * vA.x; acc0.y += dA * vA.y;
        acc0.z += dA * vA.z; acc0.w += dA * vA.w;
        acc1.x += dB * vB.x; acc1.y += dB * vB.y;
        acc1.z += dB * vB.z; acc1.w += dB * vB.w;
    }
    if (e < dg) {
        int s  = __ldg(&g_csr[s0 + e]);
        int xi = __ldg(x + s);
        float ds = __ldg(&g_dinv[s]);
        float4 v = h4_to_f4(
            ((const unsigned long long*)(g_T1h + (size_t)xi * D))[c]);
        acc0.x += ds * v.x; acc0.y += ds * v.y;
        acc0.z += ds * v.z; acc0.w += ds * v.w;
    }
    float4 acc;
    acc.x = acc0.x + acc1.x; acc.y = acc0.y + acc1.y;
    acc.z = acc0.z + acc1.z; acc.w = acc0.w + acc1.w;

    acc.x += __shfl_down_sync(0xffffffffu, acc.x, 16);
    acc.y += __shfl_down_sync(0xffffffffu, acc.y, 16);
    acc.z += __shfl_down_sync(0xffffffffu, acc.z, 16);
    acc.w += __shfl_down_sync(0xffffffffu, acc.w, 16);

    if (half == 0) {
        float di = g_dinv[warp];
        int xi = __ldg(x + warp);
        float4 a = h4_to_f4(
            ((const unsigned long long*)(g_T1h + (size_t)xi * D))[c]);
        float4 bb = __ldg((const float4*)bias + c);
        float4 h;
        h.x = fmaxf(di * (di * a.x + acc.x) + bb.x, 0.f);
        h.y = fmaxf(di * (di * a.y + acc.y) + bb.y, 0.f);
        h.z = fmaxf(di * (di * a.z + acc.z) + bb.z, 0.f);
        h.w = fmaxf(di * (di * a.w + acc.w) + bb.w, 0.f);
        ((float4*)g_bufB)[(size_t)warp * 16 + c] = h;
    }
}

// ---------------- GEMM layer 2 via tensor cores (tf32 mma.sync) -------------
// Ah = dinv * (h @ W2). Warp tile: 16 nodes x 64 cols.
// A = bufB rows (fp32 -> tf32 in-register); B = W2 fragments pre-baked in SMEM.
// m16n8k8 fragment maps: A a0..a3 = A[g][t], A[g+8][t], A[g][t+4], A[g+8][t+4];
// B b0,b1 = B[t][g], B[t+4][g]; C c0..c3 = C[g][2t], C[g][2t+1], C[g+8][2t],
// C[g+8][2t+1]   (g = lane>>2, t = lane&3).
__global__ void __launch_bounds__(256)
k_gemm2(const float* __restrict__ W) {
    __shared__ unsigned Wfrag[8][8][32][2];   // [nt][kt][lane][b0/b1], 16 KB

    int tid = threadIdx.x;
    for (int i = tid; i < 2048; i += 256) {
        int lane = i & 31;
        int kt   = (i >> 5) & 7;
        int nt   = i >> 8;
        int t = lane & 3, g = lane >> 2;
        int k0 = kt * 8 + t, n = nt * 8 + g;
        Wfrag[nt][kt][lane][0] = cvt_tf32(__ldg(W + k0 * 64 + n));
        Wfrag[nt][kt][lane][1] = cvt_tf32(__ldg(W + (k0 + 4) * 64 + n));
    }
    __syncthreads();

    int w    = tid >> 5;
    int lane = tid & 31;
    int n0   = blockIdx.x * 128 + w * 16;
    if (n0 + 16 > N_NODES) return;       // N_NODES % 16 == 0: all-or-nothing
    int t = lane & 3, g = lane >> 2;

    const float* A0 = g_bufB + (size_t)(n0 + g) * 64;
    const float* A8 = g_bufB + (size_t)(n0 + g + 8) * 64;

    float acc[8][4];
    #pragma unroll
    for (int nt = 0; nt < 8; nt++)
        #pragma unroll
        for (int j = 0; j < 4; j++) acc[nt][j] = 0.f;

    #pragma unroll
    for (int kt = 0; kt < 8; kt++) {
        unsigned a0 = cvt_tf32(__ldg(A0 + kt * 8 + t));
        unsigned a1 = cvt_tf32(__ldg(A8 + kt * 8 + t));
        unsigned a2 = cvt_tf32(__ldg(A0 + kt * 8 + t + 4));
        unsigned a3 = cvt_tf32(__ldg(A8 + kt * 8 + t + 4));
        #pragma unroll
        for (int nt = 0; nt < 8; nt++) {
            unsigned b0 = Wfrag[nt][kt][lane][0];
            unsigned b1 = Wfrag[nt][kt][lane][1];
            asm volatile(
                "mma.sync.aligned.m16n8k8.row.col.f32.tf32.tf32.f32 "
                "{%0,%1,%2,%3}, {%4,%5,%6,%7}, {%8,%9}, {%0,%1,%2,%3};"
                : "+f"(acc[nt][0]), "+f"(acc[nt][1]),
                  "+f"(acc[nt][2]), "+f"(acc[nt][3])
                : "r"(a0), "r"(a1), "r"(a2), "r"(a3), "r"(b0), "r"(b1));
        }
    }

    float d0 = g_dinv[n0 + g];
    float d8 = g_dinv[n0 + g + 8];
    #pragma unroll
    for (int nt = 0; nt < 8; nt++) {
        __half2 h0 = __floats2half2_rn(acc[nt][0] * d0, acc[nt][1] * d0);
        __half2 h8 = __floats2half2_rn(acc[nt][2] * d8, acc[nt][3] * d8);
        *(__half2*)(g_bufAh + (size_t)(n0 + g) * 64 + nt * 8 + 2 * t) = h0;
        *(__half2*)(g_bufAh + (size_t)(n0 + g + 8) * 64 + nt * 8 + 2 * t) = h8;
    }
}

// ------- gather layer 2 + pool: gsum[b] += relu(dinv*(A_i+agg)+b2) ----------
__global__ void __launch_bounds__(256)
k_gather2(const int* __restrict__ batch, const float* __restrict__ bias) {
    int warp = (blockIdx.x * blockDim.x + threadIdx.x) >> 5;
    if (warp >= N_NODES) return;
    int lane = threadIdx.x & 31;
    int half = lane >> 4;
    int c    = lane & 15;

    int s0 = g_start[warp];
    int dg = g_deg[warp];

    float4 acc0 = make_float4(0.f, 0.f, 0.f, 0.f);
    float4 acc1 = make_float4(0.f, 0.f, 0.f, 0.f);
    int e = half;
    for (; e + 2 < dg; e += 4) {
        int sA = __ldg(&g_csr[s0 + e]);
        int sB = __ldg(&g_csr[s0 + e + 2]);
        unsigned long long rA =
            ((const unsigned long long*)(g_bufAh + (size_t)sA * D))[c];
        unsigned long long rB =
            ((const unsigned long long*)(g_bufAh + (size_t)sB * D))[c];
        float4 vA = h4_to_f4(rA);
        float4 vB = h4_to_f4(rB);
        acc0.x += vA.x; acc0.y += vA.y; acc0.z += vA.z; acc0.w += vA.w;
        acc1.x += vB.x; acc1.y += vB.y; acc1.z += vB.z; acc1.w += vB.w;
    }
    if (e < dg) {
        int s = __ldg(&g_csr[s0 + e]);
        float4 v = h4_to_f4(
            ((const unsigned long long*)(g_bufAh + (size_t)s * D))[c]);
        acc0.x += v.x; acc0.y += v.y; acc0.z += v.z; acc0.w += v.w;
    }
    float4 acc;
    acc.x = acc0.x + acc1.x; acc.y = acc0.y + acc1.y;
    acc.z = acc0.z + acc1.z; acc.w = acc0.w + acc1.w;

    acc.x += __shfl_down_sync(0xffffffffu, acc.x, 16);
    acc.y += __shfl_down_sync(0xffffffffu, acc.y, 16);
    acc.z += __shfl_down_sync(0xffffffffu, acc.z, 16);
    acc.w += __shfl_down_sync(0xffffffffu, acc.w, 16);

    if (half == 0) {
        float di = g_dinv[warp];
        int b = __ldg(batch + warp);
        float4 a = h4_to_f4(
            ((const unsigned long long*)(g_bufAh + (size_t)warp * D))[c]);
        float4 bb = __ldg((const float4*)bias + c);
        float4 v;
        v.x = fmaxf(di * (a.x + acc.x) + bb.x, 0.f);
        v.y = fmaxf(di * (a.y + acc.y) + bb.y, 0.f);
        v.z = fmaxf(di * (a.z + acc.z) + bb.z, 0.f);
        v.w = fmaxf(di * (a.w + acc.w) + bb.w, 0.f);
        red_add_v4(&g_gsum[b * D + c * 4], v);
        if (c == 0) atomicAdd(&g_gcnt[b], 1.0f);
    }
}

// ---------------- head: out[g] = (gsum[g]/cnt) @ Wlin + blin ----------------
__global__ void k_final(const float* __restrict__ Wlin,
                        const float* __restrict__ blin,
                        float* __restrict__ out) {
    int g = blockIdx.x * blockDim.x + threadIdx.x;
    if (g >= NUM_GRAPHS) return;
    float inv = 1.0f / fmaxf(g_gcnt[g], 1.0f);
    float a0 = blin[0], a1 = blin[1];
    #pragma unroll
    for (int j = 0; j < D; j++) {
        float v = g_gsum[g * D + j] * inv;
        a0 += v * Wlin[2 * j + 0];
        a1 += v * Wlin[2 * j + 1];
    }
    out[2 * g + 0] = a0;
    out[2 * g + 1] = a1;
}

// ---------------- launch ----------------------------------------------------
extern "C" void kernel_launch(void* const* d_in, const int* in_sizes, int n_in,
                              void* d_out, int out_size) {
    const int*   x     = (const int*)  d_in[0];
    const int*   ei    = (const int*)  d_in[1];
    const int*   batch = (const int*)  d_in[3];
    const float* table = (const float*)d_in[4];
    const float* W1    = (const float*)d_in[5];
    const float* b1    = (const float*)d_in[6];
    const float* W2    = (const float*)d_in[7];
    const float* b2    = (const float*)d_in[8];
    const float* Wlin  = (const float*)d_in[9];
    const float* blin  = (const float*)d_in[10];
    float*       out   = (float*)d_out;

    int E = in_sizes[1] / 2;
    const int* src = ei;       // edge_index[0]
    const int* dst = ei + E;   // edge_index[1]

    const int TPB = 256;
    int gbN = (N_NODES + TPB - 1) / TPB;                         // 782
    int gbE = (E + TPB - 1) / TPB;
    int gbW = (int)(((long long)N_NODES * 32 + TPB - 1) / TPB);  // warp/node
    int gbV = (VOCAB + TPB - 1) / TPB;                           // 40
    int gbM = (N_NODES + 127) / 128;                             // 1563 (mma gemm2)

    // Fork a second branch for the CSR build (independent of T1).
    cudaStream_t s2;
    cudaEvent_t evFork, evJoin;
    cudaStreamCreateWithFlags(&s2, cudaStreamNonBlocking);
    cudaEventCreateWithFlags(&evFork, cudaEventDisableTiming);
    cudaEventCreateWithFlags(&evJoin, cudaEventDisableTiming);

    cudaEventRecord(evFork, 0);
    cudaStreamWaitEvent(s2, evFork, 0);

    // branch A (s2): CSR build + dinv
    k_init<<<gbN, TPB, 0, s2>>>();
    k_deg<<<gbE, TPB, 0, s2>>>(dst, E);
    k_scan1<<<NB_SCAN, SCAN_B, 0, s2>>>();
    k_scan2<<<1, 1024, 0, s2>>>();
    k_scan3<<<NB_SCAN, SCAN_B, 0, s2>>>();
    k_fill<<<gbE, TPB, 0, s2>>>(src, dst, E);

    // branch B (main stream): tiny vocab-level transform
    k_t1<<<gbV, TPB>>>(table, W1);                 // T1h = table @ W1 (fp16)

    // join
    cudaEventRecord(evJoin, s2);
    cudaStreamWaitEvent(0, evJoin, 0);

    k_gather1<<<gbW, TPB>>>(x, b1);                // B = relu(di*(di*T1[x_i]+Σ ds*T1[xs])+b1)
    k_gemm2<<<gbM, TPB>>>(W2);                     // Ah = dinv*(B@W2)  (tensor-core tf32)
    k_gather2<<<gbW, TPB>>>(batch, b2);            // gsum += relu(dinv*(A_i+ΣA_s)+b2)
    k_final<<<(NUM_GRAPHS + TPB - 1) / TPB, TPB>>>(Wlin, blin, out);

    cudaEventDestroy(evFork);
    cudaEventDestroy(evJoin);
    cudaStreamDestroy(s2);
}

// round 17
// speedup vs baseline: 1.3109x; 1.0771x over previous
#include <cuda_runtime.h>
#include <cuda_bf16.h>
#include <cuda_fp16.h>

#define N_NODES    200000
#define NUM_GRAPHS 2000
#define VOCAB      10000
#define D          64
#define NT         4     // nodes per thread (T1 kernel)
#define MAX_E      1600000
#define SCAN_B     256
#define NB_SCAN    ((N_NODES + SCAN_B - 1) / SCAN_B)   // 782

// ---------------- scratch (static device globals; no allocation) ------------
__device__ __half g_T1h [(size_t)VOCAB * D];    // embed_table @ W1 (fp16 storage)
__device__ __half g_bufAh[(size_t)N_NODES * D]; // layer-2 ts (fp16 storage)
__device__ float  g_bufB[(size_t)N_NODES * D];  // h (layer-1 activations, fp32)
__device__ float  g_dinv[N_NODES];
__device__ int    g_deg [N_NODES];
__device__ int    g_start[N_NODES];             // CSR row offsets (by dst)
__device__ int    g_cursor[N_NODES];
__device__ int    g_csr[MAX_E];                 // src indices bucketed by dst
__device__ int    g_bsum[NB_SCAN];
__device__ float  g_gsum[NUM_GRAPHS * D];
__device__ float  g_gcnt[NUM_GRAPHS];

// vectorized no-return global reduction (sm_90+)
__device__ __forceinline__ void red_add_v4(float* addr, float4 v) {
    asm volatile("red.global.add.v4.f32 [%0], {%1, %2, %3, %4};"
                 :: "l"(addr), "f"(v.x), "f"(v.y), "f"(v.z), "f"(v.w)
                 : "memory");
}

// ---------------- packed f32x2 helpers (sm_103a FFMA2 path) -----------------
__device__ __forceinline__ unsigned long long pack2(float v) {
    unsigned long long r;
    asm("mov.b64 %0, {%1, %1};" : "=l"(r) : "f"(v));
    return r;
}
__device__ __forceinline__ void ffma2(unsigned long long& d,
                                      unsigned long long a,
                                      unsigned long long b) {
    asm("fma.rn.f32x2 %0, %1, %2, %0;" : "+l"(d) : "l"(a), "l"(b));
}

// ---------------- fp16 / tf32 helpers ---------------------------------------
__device__ __forceinline__ float4 h4_to_f4(unsigned long long v) {
    union { unsigned long long u; __half2 h[2]; } cv;
    cv.u = v;
    float2 f0 = __half22float2(cv.h[0]);
    float2 f1 = __half22float2(cv.h[1]);
    return make_float4(f0.x, f0.y, f1.x, f1.y);
}
__device__ __forceinline__ unsigned int f32x2_to_h2(unsigned long long p) {
    union { unsigned long long u; float f[2]; } cv;
    cv.u = p;
    __half2 h = __float22half2_rn(make_float2(cv.f[0], cv.f[1]));
    return *reinterpret_cast<unsigned int*>(&h);
}
__device__ __forceinline__ unsigned cvt_tf32(float f) {
    unsigned r;
    asm("cvt.rna.tf32.f32 %0, %1;" : "=r"(r) : "f"(f));
    return r;
}

// ---------------- init: zero deg / gsum / gcnt ------------------------------
__global__ void k_init() {
    int t = blockIdx.x * blockDim.x + threadIdx.x;
    if (t < N_NODES)        g_deg[t]  = 0;
    if (t < NUM_GRAPHS * D) g_gsum[t] = 0.0f;
    if (t < NUM_GRAPHS)     g_gcnt[t] = 0.0f;
}

// ---------------- degree (in-degree over dst) -------------------------------
__global__ void k_deg(const int* __restrict__ dst, int E) {
    int e = blockIdx.x * blockDim.x + threadIdx.x;
    if (e < E) atomicAdd(&g_deg[dst[e]], 1);
}

// ---------------- CSR build: scan + fill ------------------------------------
__global__ void k_scan1() {
    __shared__ int s[SCAN_B];
    int tid = threadIdx.x;
    int t = blockIdx.x * SCAN_B + tid;
    int v = (t < N_NODES) ? g_deg[t] : 0;
    s[tid] = v;
    __syncthreads();
    #pragma unroll
    for (int o = 1; o < SCAN_B; o <<= 1) {
        int u = (tid >= o) ? s[tid - o] : 0;
        __syncthreads();
        s[tid] += u;
        __syncthreads();
    }
    if (t < N_NODES) g_start[t] = s[tid] - v;     // exclusive
    if (tid == SCAN_B - 1) g_bsum[blockIdx.x] = s[tid];
}

__global__ void k_scan2() {
    __shared__ int s[1024];
    int tid = threadIdx.x;
    int v = (tid < NB_SCAN) ? g_bsum[tid] : 0;
    s[tid] = v;
    __syncthreads();
    #pragma unroll
    for (int o = 1; o < 1024; o <<= 1) {
        int u = (tid >= o) ? s[tid - o] : 0;
        __syncthreads();
        s[tid] += u;
        __syncthreads();
    }
    if (tid < NB_SCAN) g_bsum[tid] = s[tid] - v;  // exclusive block offsets
}

__global__ void k_scan3() {
    int t = blockIdx.x * blockDim.x + threadIdx.x;
    if (t >= N_NODES) return;
    int st = g_start[t] + g_bsum[blockIdx.x];
    g_start[t]  = st;
    g_cursor[t] = st;
    g_dinv[t]   = rsqrtf((float)(g_deg[t] + 1));  // +1 self loop
}

__global__ void k_fill(const int* __restrict__ src, const int* __restrict__ dst, int E) {
    int e = blockIdx.x * blockDim.x + threadIdx.x;
    if (e >= E) return;
    int d = dst[e];
    int pos = atomicAdd(&g_cursor[d], 1);
    g_csr[pos] = src[e];
}

// FFMA2 k-slice, 16 cols/thread (T1 kernel)
#define KSTEP2(R, COMP)                                                       \
    {                                                                         \
        const ulonglong2* wr =                                                \
            (const ulonglong2*)&Ws[(k4 * 4 + (R)) * 16 + q * 4];              \
        ulonglong2 wv0 = wr[0], wv1 = wr[1], wv2 = wr[2], wv3 = wr[3];        \
        _Pragma("unroll")                                                     \
        for (int i = 0; i < NT; i++) {                                        \
            unsigned long long hs2 = pack2(h[i].COMP);                        \
            ffma2(acc2[i][0], hs2, wv0.x);                                    \
            ffma2(acc2[i][1], hs2, wv0.y);                                    \
            ffma2(acc2[i][2], hs2, wv1.x);                                    \
            ffma2(acc2[i][3], hs2, wv1.y);                                    \
            ffma2(acc2[i][4], hs2, wv2.x);                                    \
            ffma2(acc2[i][5], hs2, wv2.y);                                    \
            ffma2(acc2[i][6], hs2, wv3.x);                                    \
            ffma2(acc2[i][7], hs2, wv3.y);                                    \
        }                                                                     \
    }

// ---------------- T1 = embed_table @ W1  (VOCAB x 64, fp16 out) -------------
__global__ void __launch_bounds__(256, 2)
k_t1(const float* __restrict__ table, const float* __restrict__ W) {
    __shared__ float4 Ws[D * 16];   // W row-major: Ws[k*16 + j4]
    for (int t = threadIdx.x; t < D * 16; t += 256)
        Ws[t] = ((const float4*)W)[t];
    __syncthreads();

    int T    = blockIdx.x * 256 + threadIdx.x;
    int lane = threadIdx.x & 31;
    int q    = lane & 3;
    int r8   = lane >> 2;
    int wb   = (T >> 5) * 32;

    int n[NT];
    const float4* hrow[NT];
    #pragma unroll
    for (int i = 0; i < NT; i++) {
        n[i] = wb + r8 + i * 8;
        int ns = (n[i] < VOCAB) ? n[i] : 0;
        hrow[i] = (const float4*)(table + (size_t)ns * D);
    }

    unsigned long long acc2[NT][8];
    #pragma unroll
    for (int i = 0; i < NT; i++)
        #pragma unroll
        for (int j = 0; j < 8; j++) acc2[i][j] = 0ull;

    #pragma unroll 4
    for (int k4 = 0; k4 < 16; k4++) {
        float4 h[NT];
        #pragma unroll
        for (int i = 0; i < NT; i++) h[i] = hrow[i][k4];
        KSTEP2(0, x)
        KSTEP2(1, y)
        KSTEP2(2, z)
        KSTEP2(3, w)
    }

    #pragma unroll
    for (int i = 0; i < NT; i++) {
        if (n[i] >= VOCAB) continue;
        uint4* O = (uint4*)(g_T1h + (size_t)n[i] * D) + q * 2;
        O[0] = make_uint4(f32x2_to_h2(acc2[i][0]), f32x2_to_h2(acc2[i][1]),
                          f32x2_to_h2(acc2[i][2]), f32x2_to_h2(acc2[i][3]));
        O[1] = make_uint4(f32x2_to_h2(acc2[i][4]), f32x2_to_h2(acc2[i][5]),
                          f32x2_to_h2(acc2[i][6]), f32x2_to_h2(acc2[i][7]));
    }
}

// ---- gather layer 1: h = relu(di*(di*T1[x_i] + Σ dinv[s]*T1[x[s]]) + b1) ---
// One 16-lane group per node (2 nodes/warp). Lane c owns 4 cols (8 B fp16).
// 2-way manual software pipelining; no cross-group reduction needed.
__global__ void __launch_bounds__(256)
k_gather1(const int* __restrict__ x, const float* __restrict__ bias) {
    int node = (blockIdx.x * blockDim.x + threadIdx.x) >> 4;
    if (node >= N_NODES) return;
    int c = threadIdx.x & 15;

    int s0 = g_start[node];
    int dg = g_deg[node];

    float4 acc0 = make_float4(0.f, 0.f, 0.f, 0.f);
    float4 acc1 = make_float4(0.f, 0.f, 0.f, 0.f);
    int e = 0;
    for (; e + 1 < dg; e += 2) {
        int sA = __ldg(&g_csr[s0 + e]);
        int sB = __ldg(&g_csr[s0 + e + 1]);
        int xA = __ldg(x + sA);
        int xB = __ldg(x + sB);
        float dA = __ldg(&g_dinv[sA]);
        float dB = __ldg(&g_dinv[sB]);
        unsigned long long rA =
            ((const unsigned long long*)(g_T1h + (size_t)xA * D))[c];
        unsigned long long rB =
            ((const unsigned long long*)(g_T1h + (size_t)xB * D))[c];
        float4 vA = h4_to_f4(rA);
        float4 vB = h4_to_f4(rB);
        acc0.x += dA * vA.x; acc0.y += dA * vA.y;
        acc0.z += dA * vA.z; acc0.w += dA * vA.w;
        acc1.x += dB * vB.x; acc1.y += dB * vB.y;
        acc1.z += dB * vB.z; acc1.w += dB * vB.w;
    }
    if (e < dg) {
        int s  = __ldg(&g_csr[s0 + e]);
        int xi = __ldg(x + s);
        float ds = __ldg(&g_dinv[s]);
        float4 v = h4_to_f4(
            ((const unsigned long long*)(g_T1h + (size_t)xi * D))[c]);
        acc0.x += ds * v.x; acc0.y += ds * v.y;
        acc0.z += ds * v.z; acc0.w += ds * v.w;
    }

    float di = g_dinv[node];
    int xi = __ldg(x + node);
    float4 a = h4_to_f4(
        ((const unsigned long long*)(g_T1h + (size_t)xi * D))[c]);
    float4 bb = __ldg((const float4*)bias + c);
    float4 h;
    h.x = fmaxf(di * (di * a.x + acc0.x + acc1.x) + bb.x, 0.f);
    h.y = fmaxf(di * (di * a.y + acc0.y + acc1.y) + bb.y, 0.f);
    h.z = fmaxf(di * (di * a.z + acc0.z + acc1.z) + bb.z, 0.f);
    h.w = fmaxf(di * (di * a.w + acc0.w + acc1.w) + bb.w, 0.f);
    ((float4*)g_bufB)[(size_t)node * 16 + c] = h;
}

// ---------------- GEMM layer 2 via tensor cores (tf32 mma.sync) -------------
// Ah = dinv * (h @ W2). Warp tile: 16 nodes x 64 cols. (R16-validated)
__global__ void __launch_bounds__(256)
k_gemm2(const float* __restrict__ W) {
    __shared__ unsigned Wfrag[8][8][32][2];   // [nt][kt][lane][b0/b1], 16 KB

    int tid = threadIdx.x;
    for (int i = tid; i < 2048; i += 256) {
        int lane = i & 31;
        int kt   = (i >> 5) & 7;
        int nt   = i >> 8;
        int t = lane & 3, g = lane >> 2;
        int k0 = kt * 8 + t, n = nt * 8 + g;
        Wfrag[nt][kt][lane][0] = cvt_tf32(__ldg(W + k0 * 64 + n));
        Wfrag[nt][kt][lane][1] = cvt_tf32(__ldg(W + (k0 + 4) * 64 + n));
    }
    __syncthreads();

    int w    = tid >> 5;
    int lane = tid & 31;
    int n0   = blockIdx.x * 128 + w * 16;
    if (n0 + 16 > N_NODES) return;       // N_NODES % 16 == 0: all-or-nothing
    int t = lane & 3, g = lane >> 2;

    const float* A0 = g_bufB + (size_t)(n0 + g) * 64;
    const float* A8 = g_bufB + (size_t)(n0 + g + 8) * 64;

    float acc[8][4];
    #pragma unroll
    for (int nt = 0; nt < 8; nt++)
        #pragma unroll
        for (int j = 0; j < 4; j++) acc[nt][j] = 0.f;

    #pragma unroll
    for (int kt = 0; kt < 8; kt++) {
        unsigned a0 = cvt_tf32(__ldg(A0 + kt * 8 + t));
        unsigned a1 = cvt_tf32(__ldg(A8 + kt * 8 + t));
        unsigned a2 = cvt_tf32(__ldg(A0 + kt * 8 + t + 4));
        unsigned a3 = cvt_tf32(__ldg(A8 + kt * 8 + t + 4));
        #pragma unroll
        for (int nt = 0; nt < 8; nt++) {
            unsigned b0 = Wfrag[nt][kt][lane][0];
            unsigned b1 = Wfrag[nt][kt][lane][1];
            asm volatile(
                "mma.sync.aligned.m16n8k8.row.col.f32.tf32.tf32.f32 "
                "{%0,%1,%2,%3}, {%4,%5,%6,%7}, {%8,%9}, {%0,%1,%2,%3};"
                : "+f"(acc[nt][0]), "+f"(acc[nt][1]),
                  "+f"(acc[nt][2]), "+f"(acc[nt][3])
                : "r"(a0), "r"(a1), "r"(a2), "r"(a3), "r"(b0), "r"(b1));
        }
    }

    float d0 = g_dinv[n0 + g];
    float d8 = g_dinv[n0 + g + 8];
    #pragma unroll
    for (int nt = 0; nt < 8; nt++) {
        __half2 h0 = __floats2half2_rn(acc[nt][0] * d0, acc[nt][1] * d0);
        __half2 h8 = __floats2half2_rn(acc[nt][2] * d8, acc[nt][3] * d8);
        *(__half2*)(g_bufAh + (size_t)(n0 + g) * 64 + nt * 8 + 2 * t) = h0;
        *(__half2*)(g_bufAh + (size_t)(n0 + g + 8) * 64 + nt * 8 + 2 * t) = h8;
    }
}

// ------- gather layer 2 + pool: gsum[b] += relu(dinv*(A_i+agg)+b2) ----------
// One 16-lane group per node (2 nodes/warp), same structure as gather1.
__global__ void __launch_bounds__(256)
k_gather2(const int* __restrict__ batch, const float* __restrict__ bias) {
    int node = (blockIdx.x * blockDim.x + threadIdx.x) >> 4;
    if (node >= N_NODES) return;
    int c = threadIdx.x & 15;

    int s0 = g_start[node];
    int dg = g_deg[node];

    float4 acc0 = make_float4(0.f, 0.f, 0.f, 0.f);
    float4 acc1 = make_float4(0.f, 0.f, 0.f, 0.f);
    int e = 0;
    for (; e + 1 < dg; e += 2) {
        int sA = __ldg(&g_csr[s0 + e]);
        int sB = __ldg(&g_csr[s0 + e + 1]);
        unsigned long long rA =
            ((const unsigned long long*)(g_bufAh + (size_t)sA * D))[c];
        unsigned long long rB =
            ((const unsigned long long*)(g_bufAh + (size_t)sB * D))[c];
        float4 vA = h4_to_f4(rA);
        float4 vB = h4_to_f4(rB);
        acc0.x += vA.x; acc0.y += vA.y; acc0.z += vA.z; acc0.w += vA.w;
        acc1.x += vB.x; acc1.y += vB.y; acc1.z += vB.z; acc1.w += vB.w;
    }
    if (e < dg) {
        int s = __ldg(&g_csr[s0 + e]);
        float4 v = h4_to_f4(
            ((const unsigned long long*)(g_bufAh + (size_t)s * D))[c]);
        acc0.x += v.x; acc0.y += v.y; acc0.z += v.z; acc0.w += v.w;
    }

    float di = g_dinv[node];
    int b = __ldg(batch + node);
    float4 a = h4_to_f4(
        ((const unsigned long long*)(g_bufAh + (size_t)node * D))[c]);
    float4 bb = __ldg((const float4*)bias + c);
    float4 v;
    v.x = fmaxf(di * (a.x + acc0.x + acc1.x) + bb.x, 0.f);
    v.y = fmaxf(di * (a.y + acc0.y + acc1.y) + bb.y, 0.f);
    v.z = fmaxf(di * (a.z + acc0.z + acc1.z) + bb.z, 0.f);
    v.w = fmaxf(di * (a.w + acc0.w + acc1.w) + bb.w, 0.f);
    red_add_v4(&g_gsum[b * D + c * 4], v);
    if (c == 0) atomicAdd(&g_gcnt[b], 1.0f);
}

// ---------------- head: out[g] = (gsum[g]/cnt) @ Wlin + blin ----------------
__global__ void k_final(const float* __restrict__ Wlin,
                        const float* __restrict__ blin,
                        float* __restrict__ out) {
    int g = blockIdx.x * blockDim.x + threadIdx.x;
    if (g >= NUM_GRAPHS) return;
    float inv = 1.0f / fmaxf(g_gcnt[g], 1.0f);
    float a0 = blin[0], a1 = blin[1];
    #pragma unroll
    for (int j = 0; j < D; j++) {
        float v = g_gsum[g * D + j] * inv;
        a0 += v * Wlin[2 * j + 0];
        a1 += v * Wlin[2 * j + 1];
    }
    out[2 * g + 0] = a0;
    out[2 * g + 1] = a1;
}

// ---------------- launch ----------------------------------------------------
extern "C" void kernel_launch(void* const* d_in, const int* in_sizes, int n_in,
                              void* d_out, int out_size) {
    const int*   x     = (const int*)  d_in[0];
    const int*   ei    = (const int*)  d_in[1];
    const int*   batch = (const int*)  d_in[3];
    const float* table = (const float*)d_in[4];
    const float* W1    = (const float*)d_in[5];
    const float* b1    = (const float*)d_in[6];
    const float* W2    = (const float*)d_in[7];
    const float* b2    = (const float*)d_in[8];
    const float* Wlin  = (const float*)d_in[9];
    const float* blin  = (const float*)d_in[10];
    float*       out   = (float*)d_out;

    int E = in_sizes[1] / 2;
    const int* src = ei;       // edge_index[0]
    const int* dst = ei + E;   // edge_index[1]

    const int TPB = 256;
    int gbN = (N_NODES + TPB - 1) / TPB;                         // 782
    int gbE = (E + TPB - 1) / TPB;
    int gbG = (int)(((long long)N_NODES * 16 + TPB - 1) / TPB);  // 12500 (gathers)
    int gbV = (VOCAB + TPB - 1) / TPB;                           // 40
    int gbM = (N_NODES + 127) / 128;                             // 1563 (mma gemm2)

    // Fork a second branch for the CSR build (independent of T1).
    cudaStream_t s2;
    cudaEvent_t evFork, evJoin;
    cudaStreamCreateWithFlags(&s2, cudaStreamNonBlocking);
    cudaEventCreateWithFlags(&evFork, cudaEventDisableTiming);
    cudaEventCreateWithFlags(&evJoin, cudaEventDisableTiming);

    cudaEventRecord(evFork, 0);
    cudaStreamWaitEvent(s2, evFork, 0);

    // branch A (s2): CSR build + dinv
    k_init<<<gbN, TPB, 0, s2>>>();
    k_deg<<<gbE, TPB, 0, s2>>>(dst, E);
    k_scan1<<<NB_SCAN, SCAN_B, 0, s2>>>();
    k_scan2<<<1, 1024, 0, s2>>>();
    k_scan3<<<NB_SCAN, SCAN_B, 0, s2>>>();
    k_fill<<<gbE, TPB, 0, s2>>>(src, dst, E);

    // branch B (main stream): tiny vocab-level transform
    k_t1<<<gbV, TPB>>>(table, W1);                 // T1h = table @ W1 (fp16)

    // join
    cudaEventRecord(evJoin, s2);
    cudaStreamWaitEvent(0, evJoin, 0);

    k_gather1<<<gbG, TPB>>>(x, b1);                // B = relu(di*(di*T1[x_i]+Σ ds*T1[xs])+b1)
    k_gemm2<<<gbM, TPB>>>(W2);                     // Ah = dinv*(B@W2)  (tensor-core tf32)
    k_gather2<<<gbG, TPB>>>(batch, b2);            // gsum += relu(dinv*(A_i+ΣA_s)+b2)
    k_final<<<(NUM_GRAPHS + TPB - 1) / TPB, TPB>>>(Wlin, blin, out);

    cudaEventDestroy(evFork);
    cudaEventDestroy(evJoin);
    cudaStreamDestroy(s2);
}